// round 4
// baseline (speedup 1.0000x reference)
#include <cuda_runtime.h>
#include <cuda_fp16.h>

// Bilinear flow warp. input1: [B,C,H,W] fp32, flow: [B,2,H,W] fp32.
// Fixed shapes: B=8, C=64, H=256, W=448.
//
// Pass A: NCHW fp32 -> NHWC fp16 scratch (halved scratch traffic, full-sector stores).
// Pass B: per-pixel gather of 4 corners (corner = 64 contiguous fp16 channels =
//         128B = one L1 wavefront per warp), fp32 math, fp16 smem result tile,
//         transposed NCHW fp32 writeback. All global accesses coalesced.

#define B_   8
#define C_   64
#define H_   256
#define W_   448
#define HW_  (H_ * W_)            // 114688
#define CHW_ (C_ * HW_)           // 7340032
#define PX_TILE 128
#define TILES_PER_B (HW_ / PX_TILE)   // 896  (HW divisible by 128; tiles may cross rows, handled per-pixel)

// ~117 MB scratch: input in NHWC fp16 layout [B, H, W, C]
__device__ static __half g_nhwc[(size_t)B_ * HW_ * C_];

// ---------------------------------------------------------------------------
// Kernel A: NCHW fp32 -> NHWC fp16.  Tile = 64 ch x 128 px, 512 threads.
// ---------------------------------------------------------------------------
__global__ void __launch_bounds__(512) nchw_to_nhwc_f16(const float* __restrict__ in)
{
    __shared__ float sm[64 * 129];   // [c][px], row stride 129

    int blk  = blockIdx.x;
    int b    = blk / TILES_PER_B;
    int tile = blk - b * TILES_PER_B;
    int px0  = tile * PX_TILE;
    int tid  = threadIdx.x;

    // ---- load: float4 per thread; warp = 32 lanes x 16B consecutive px ----
    {
        int c_lo = tid >> 5;             // 0..15
        int px4  = (tid & 31) * 4;       // 0..124
        const float* src = in + b * CHW_ + px0 + px4;
        #pragma unroll
        for (int it = 0; it < 4; ++it) {
            int c = it * 16 + c_lo;
            float4 v = *(const float4*)(src + c * HW_);
            float* s = sm + c * 129 + px4;
            s[0] = v.x; s[1] = v.y; s[2] = v.z; s[3] = v.w;
        }
    }
    __syncthreads();

    // ---- store: chunk = 8 channels (16B fp16). 1024 chunks, 2 per thread.
    //      Warp covers 4 px x full 128B row: perfectly contiguous 512B stores.
    {
        #pragma unroll
        for (int k = 0; k < 2; ++k) {
            int idx = k * 512 + tid;
            int px  = idx >> 3;          // 0..127
            int c16 = idx & 7;           // 8-channel chunk
            const float* col = sm + (c16 * 8) * 129 + px;
            unsigned int u[4];
            #pragma unroll
            for (int j = 0; j < 4; ++j) {
                float a0 = col[(2 * j)     * 129];
                float a1 = col[(2 * j + 1) * 129];
                __half2 h = __floats2half2_rn(a0, a1);
                u[j] = *(unsigned int*)&h;
            }
            __half* dst = g_nhwc + (size_t)(b * HW_ + px0 + px) * 64 + c16 * 8;
            *(uint4*)dst = make_uint4(u[0], u[1], u[2], u[3]);
        }
    }
}

// ---------------------------------------------------------------------------
// Kernel B: gather from NHWC fp16, write NCHW fp32.
// Block = 512 threads handles 128 consecutive pixels x all 64 channels.
// ---------------------------------------------------------------------------
__global__ void __launch_bounds__(512) warp_gather_f16(
    const float* __restrict__ flow,   // [B,2,H,W]
    float* __restrict__ out)          // [B,C,H,W]
{
    __shared__ float   s_w[PX_TILE][4];     // per-pixel corner weights
    __shared__ int     s_o[PX_TILE][4];     // per-pixel corner base offsets (half index)
    __shared__ __half2 s_r[PX_TILE * 33];   // result tile: [px][c/2], row stride 33 words

    int blk  = blockIdx.x;
    int b    = blk / TILES_PER_B;
    int tile = blk - b * TILES_PER_B;
    int rem0 = tile * PX_TILE;
    int tid  = threadIdx.x;

    // ---- phase 1: 128 threads compute per-pixel weights & offsets ----
    if (tid < PX_TILE) {
        int rem = rem0 + tid;
        int h   = rem / W_;
        int w   = rem - h * W_;

        const float* fl = flow + b * 2 * HW_ + rem;
        float fx = __ldg(fl);
        float fy = __ldg(fl + HW_);

        float x = (float)w + fx;
        float y = (float)h + fy;

        float x0f = floorf(x);
        float y0f = floorf(y);
        int x0 = (int)x0f;
        int y0 = (int)y0f;
        int x1 = x0 + 1;
        int y1 = y0 + 1;

        float wx1 = x - x0f;
        float wx0 = 1.0f - wx1;
        float wy1 = y - y0f;
        float wy0 = 1.0f - wy1;

        float vx0 = (x0 >= 0 && x0 < W_) ? 1.0f : 0.0f;
        float vx1 = (x1 >= 0 && x1 < W_) ? 1.0f : 0.0f;
        float vy0 = (y0 >= 0 && y0 < H_) ? 1.0f : 0.0f;
        float vy1 = (y1 >= 0 && y1 < H_) ? 1.0f : 0.0f;

        int x0c = min(max(x0, 0), W_ - 1);
        int x1c = min(max(x1, 0), W_ - 1);
        int y0c = min(max(y0, 0), H_ - 1);
        int y1c = min(max(y1, 0), H_ - 1);

        s_w[tid][0] = wy0 * wx0 * vy0 * vx0;
        s_w[tid][1] = wy0 * wx1 * vy0 * vx1;
        s_w[tid][2] = wy1 * wx0 * vy1 * vx0;
        s_w[tid][3] = wy1 * wx1 * vy1 * vx1;

        int row0 = (b * H_ + y0c) * W_;
        int row1 = (b * H_ + y1c) * W_;
        s_o[tid][0] = (row0 + x0c) * 64;
        s_o[tid][1] = (row0 + x1c) * 64;
        s_o[tid][2] = (row1 + x0c) * 64;
        s_o[tid][3] = (row1 + x1c) * 64;
    }
    __syncthreads();

    // ---- phase 2: 16 warps x 8 pixels; lane covers channels (2*lane, 2*lane+1).
    //      Corner load = 128B/warp = 1 wavefront. Result -> fp16 smem,
    //      word index p*33+lane: conflict-free. ----
    {
        int wid  = tid >> 5;
        int lane = tid & 31;

        #pragma unroll
        for (int j = 0; j < 8; ++j) {
            int p = wid * 8 + j;
            float w00 = s_w[p][0], w01 = s_w[p][1], w10 = s_w[p][2], w11 = s_w[p][3];
            int   o00 = s_o[p][0], o01 = s_o[p][1], o10 = s_o[p][2], o11 = s_o[p][3];

            float2 v00 = __half22float2(__ldg((const __half2*)(g_nhwc + o00) + lane));
            float2 v01 = __half22float2(__ldg((const __half2*)(g_nhwc + o01) + lane));
            float2 v10 = __half22float2(__ldg((const __half2*)(g_nhwc + o10) + lane));
            float2 v11 = __half22float2(__ldg((const __half2*)(g_nhwc + o11) + lane));

            float r0 = w00 * v00.x + w01 * v01.x + w10 * v10.x + w11 * v11.x;
            float r1 = w00 * v00.y + w01 * v01.y + w10 * v10.y + w11 * v11.y;

            s_r[p * 33 + lane] = __floats2half2_rn(r0, r1);
        }
    }
    __syncthreads();

    // ---- phase 3: coalesced NCHW fp32 writeback.
    //      Thread (subc, px): reads half at px*66+c (word stride 33: conflict-free). ----
    {
        const __half* sh = (const __half*)s_r;
        int subc = tid >> 7;            // 0..3
        int px   = tid & 127;           // 0..127
        float* dst = out + b * CHW_ + rem0 + px;
        #pragma unroll
        for (int it = 0; it < 16; ++it) {
            int c = it * 4 + subc;
            dst[c * HW_] = __half2float(sh[px * 66 + c]);
        }
    }
}

extern "C" void kernel_launch(void* const* d_in, const int* in_sizes, int n_in,
                              void* d_out, int out_size)
{
    const float* img  = (const float*)d_in[0];
    const float* flow = (const float*)d_in[1];
    float* out = (float*)d_out;

    const int blocks = B_ * TILES_PER_B;   // 7168
    nchw_to_nhwc_f16<<<blocks, 512>>>(img);
    warp_gather_f16<<<blocks, 512>>>(flow, out);
}

// round 5
// speedup vs baseline: 1.1222x; 1.1222x over previous
#include <cuda_runtime.h>
#include <cuda_fp16.h>

// Bilinear flow warp. input1: [B,C,H,W] fp32, flow: [B,2,H,W] fp32.
// Fixed shapes: B=8, C=64, H=256, W=448.
//
// Pass A: NCHW fp32 -> NHWC fp16 scratch (full-width load & store wavefronts).
// Pass B: per-pixel gather of 4 corners (corner = 64 contiguous fp16 ch = 128B
//         = 1 L1 wavefront/warp), half2 FMA blend, fp16 smem tile, coalesced
//         NCHW fp32 writeback.

#define B_   8
#define C_   64
#define H_   256
#define W_   448
#define HW_  (H_ * W_)            // 114688
#define CHW_ (C_ * HW_)           // 7340032
#define TILES_PER_B (HW_ / 64)    // 1792 (W=448 divisible by 64: tile stays in one row)

// ~117 MB scratch: input in NHWC fp16 layout [B, H, W, C]
__device__ static __half g_nhwc[(size_t)B_ * HW_ * C_];

// ---------------------------------------------------------------------------
// Kernel A: NCHW fp32 -> NHWC fp16.  Tile = 64 ch x 64 px, 256 threads.
// ---------------------------------------------------------------------------
__global__ void __launch_bounds__(256) nchw_to_nhwc_f16(const float* __restrict__ in)
{
    __shared__ float sm[64 * 65];    // [c][px], row stride 65

    int blk  = blockIdx.x;
    int b    = blk / TILES_PER_B;
    int tile = blk - b * TILES_PER_B;
    int px0  = tile * 64;
    int tid  = threadIdx.x;

    // ---- load: float4 per thread (16 threads cover one channel row of 64 px) ----
    {
        int c_lo = tid >> 4;             // 0..15
        int px4  = (tid & 15) * 4;       // 0..60
        const float* src = in + b * CHW_ + px0 + px4;
        #pragma unroll
        for (int it = 0; it < 4; ++it) {
            int c = it * 16 + c_lo;
            float4 v = *(const float4*)(src + c * HW_);
            float* s = sm + c * 65 + px4;
            s[0] = v.x; s[1] = v.y; s[2] = v.z; s[3] = v.w;
        }
    }
    __syncthreads();

    // ---- store: 2048 half2 words (64 px x 32 words); 8 words per thread.
    //      Consecutive tid -> consecutive words: full 128B store wavefronts. ----
    {
        unsigned int* dst = (unsigned int*)(g_nhwc + (size_t)(b * HW_ + px0) * 64);
        #pragma unroll
        for (int k = 0; k < 8; ++k) {
            int idx = k * 256 + tid;
            int px  = idx >> 5;          // 0..63
            int cw  = idx & 31;          // channel word: channels 2cw, 2cw+1
            float a0 = sm[(2 * cw)     * 65 + px];
            float a1 = sm[(2 * cw + 1) * 65 + px];
            __half2 h = __floats2half2_rn(a0, a1);
            dst[px * 32 + cw] = *(unsigned int*)&h;
        }
    }
}

// ---------------------------------------------------------------------------
// Kernel B: gather from NHWC fp16, write NCHW fp32.
// Block = 256 threads handles 64 consecutive pixels (one row) x 64 channels.
// ---------------------------------------------------------------------------
__global__ void __launch_bounds__(256) warp_gather_f16(
    const float* __restrict__ flow,   // [B,2,H,W]
    float* __restrict__ out)          // [B,C,H,W]
{
    __shared__ __half2 s_wh[64][4];   // per-pixel corner weights, pre-broadcast half2
    __shared__ int     s_o[64][4];    // per-pixel corner base offsets (half index)
    __shared__ __half2 s_r[64 * 33];  // result tile [px][c/2], stride 33 words

    int blk  = blockIdx.x;
    int b    = blk / TILES_PER_B;
    int tile = blk - b * TILES_PER_B;
    int rem0 = tile * 64;
    int tid  = threadIdx.x;

    // ---- phase 1: one thread per (pixel, corner) ----
    {
        int px     = tid & 63;
        int corner = tid >> 6;           // 0:(y0,x0) 1:(y0,x1) 2:(y1,x0) 3:(y1,x1)
        int rem = rem0 + px;
        int h   = rem / W_;
        int w   = rem - h * W_;

        const float* fl = flow + b * 2 * HW_ + rem;
        float fx = __ldg(fl);
        float fy = __ldg(fl + HW_);

        float x = (float)w + fx;
        float y = (float)h + fy;

        float x0f = floorf(x);
        float y0f = floorf(y);

        int cx = corner & 1;
        int cy = corner >> 1;

        float wx1 = x - x0f;
        float wy1 = y - y0f;
        float wx = cx ? wx1 : (1.0f - wx1);
        float wy = cy ? wy1 : (1.0f - wy1);

        int xi = (int)x0f + cx;
        int yi = (int)y0f + cy;
        float valid = (xi >= 0 && xi < W_ && yi >= 0 && yi < H_) ? 1.0f : 0.0f;
        xi = min(max(xi, 0), W_ - 1);
        yi = min(max(yi, 0), H_ - 1);

        s_wh[px][corner] = __float2half2_rn(wx * wy * valid);
        s_o[px][corner]  = ((b * H_ + yi) * W_ + xi) * 64;
    }
    __syncthreads();

    // ---- phase 2: 8 warps x 8 pixels; lane covers channels (2*lane, 2*lane+1).
    //      4 coalesced 128B corner loads, 4 half2 FMAs, 1 conflict-free STS. ----
    {
        int wid  = tid >> 5;
        int lane = tid & 31;

        #pragma unroll
        for (int j = 0; j < 8; ++j) {
            int p = wid * 8 + j;
            __half2 w00 = s_wh[p][0], w01 = s_wh[p][1], w10 = s_wh[p][2], w11 = s_wh[p][3];
            int     o00 = s_o[p][0],  o01 = s_o[p][1],  o10 = s_o[p][2],  o11 = s_o[p][3];

            __half2 v00 = __ldg((const __half2*)(g_nhwc + o00) + lane);
            __half2 v01 = __ldg((const __half2*)(g_nhwc + o01) + lane);
            __half2 v10 = __ldg((const __half2*)(g_nhwc + o10) + lane);
            __half2 v11 = __ldg((const __half2*)(g_nhwc + o11) + lane);

            __half2 r = __hfma2(v00, w00,
                        __hfma2(v01, w01,
                        __hfma2(v10, w10,
                        __hmul2(v11, w11))));
            s_r[p * 33 + lane] = r;
        }
    }
    __syncthreads();

    // ---- phase 3: coalesced NCHW fp32 writeback.
    //      Thread (px = tid&63, cgrp = tid>>6) reads 8 half2 words (stride-33:
    //      conflict-free), stores 16 floats; warps store contiguous 128B lines. ----
    {
        int px   = tid & 63;
        int cgrp = tid >> 6;             // 0..3 -> channels 16*cgrp .. +15
        float* dst = out + b * CHW_ + rem0 + px;
        #pragma unroll
        for (int k = 0; k < 8; ++k) {
            __half2 hv = s_r[px * 33 + cgrp * 8 + k];
            float2 f = __half22float2(hv);
            int c = cgrp * 16 + 2 * k;
            dst[c * HW_]       = f.x;
            dst[(c + 1) * HW_] = f.y;
        }
    }
}

extern "C" void kernel_launch(void* const* d_in, const int* in_sizes, int n_in,
                              void* d_out, int out_size)
{
    const float* img  = (const float*)d_in[0];
    const float* flow = (const float*)d_in[1];
    float* out = (float*)d_out;

    const int blocks = B_ * TILES_PER_B;   // 14336
    nchw_to_nhwc_f16<<<blocks, 256>>>(img);
    warp_gather_f16<<<blocks, 256>>>(flow, out);
}

// round 7
// speedup vs baseline: 1.1741x; 1.0462x over previous
#include <cuda_runtime.h>
#include <cuda_fp16.h>

// Bilinear flow warp. input1: [B,C,H,W] fp32, flow: [B,2,H,W] fp32.
// Fixed shapes: B=8, C=64, H=256, W=448.
//
// Pass A: NCHW fp32 -> NHWC fp16 scratch.
// Pass B: per-pixel gather of 4 corners (corner = 64 contiguous fp16 ch = 128B
//         = 1 L1 wavefront/warp), batched loads for MLP=16/thread, half2 FMA
//         blend, fp16 smem tile, coalesced NCHW fp32 writeback.

#define B_   8
#define C_   64
#define H_   256
#define W_   448
#define HW_  (H_ * W_)            // 114688
#define CHW_ (C_ * HW_)           // 7340032
#define TILES_PER_B (HW_ / 64)    // 1792 (W=448 divisible by 64: tile stays in one row)

// ~117 MB scratch: input in NHWC fp16 layout [B, H, W, C]
__device__ static __half g_nhwc[(size_t)B_ * HW_ * C_];

// ---------------------------------------------------------------------------
// Kernel A: NCHW fp32 -> NHWC fp16.  Tile = 64 ch x 64 px, 256 threads.
// ---------------------------------------------------------------------------
__global__ void __launch_bounds__(256) nchw_to_nhwc_f16(const float* __restrict__ in)
{
    __shared__ float sm[64 * 65];    // [c][px], row stride 65

    int blk  = blockIdx.x;
    int b    = blk / TILES_PER_B;
    int tile = blk - b * TILES_PER_B;
    int px0  = tile * 64;
    int tid  = threadIdx.x;

    // ---- load: float4 per thread (16 threads cover one channel row of 64 px) ----
    {
        int c_lo = tid >> 4;             // 0..15
        int px4  = (tid & 15) * 4;       // 0..60
        const float* src = in + b * CHW_ + px0 + px4;
        #pragma unroll
        for (int it = 0; it < 4; ++it) {
            int c = it * 16 + c_lo;
            float4 v = *(const float4*)(src + c * HW_);
            float* s = sm + c * 65 + px4;
            s[0] = v.x; s[1] = v.y; s[2] = v.z; s[3] = v.w;
        }
    }
    __syncthreads();

    // ---- store: 2048 half2 words (64 px x 32 words); 8 words per thread.
    //      Consecutive tid -> consecutive words: full 128B store wavefronts. ----
    {
        unsigned int* dst = (unsigned int*)(g_nhwc + (size_t)(b * HW_ + px0) * 64);
        #pragma unroll
        for (int k = 0; k < 8; ++k) {
            int idx = k * 256 + tid;
            int px  = idx >> 5;          // 0..63
            int cw  = idx & 31;          // channel word: channels 2cw, 2cw+1
            float a0 = sm[(2 * cw)     * 65 + px];
            float a1 = sm[(2 * cw + 1) * 65 + px];
            __half2 h = __floats2half2_rn(a0, a1);
            dst[px * 32 + cw] = *(unsigned int*)&h;
        }
    }
}

// ---------------------------------------------------------------------------
// Kernel B: gather from NHWC fp16, write NCHW fp32.
// Block = 256 threads handles 64 consecutive pixels (one row) x 64 channels.
// ---------------------------------------------------------------------------
__global__ void __launch_bounds__(256) warp_gather_f16(
    const float* __restrict__ flow,   // [B,2,H,W]
    float* __restrict__ out)          // [B,C,H,W]
{
    __shared__ __half2 s_wh[64][4];   // per-pixel corner weights, pre-broadcast half2
    __shared__ int     s_o[64][4];    // per-pixel corner base offsets (half index)
    __shared__ __half2 s_r[64 * 33];  // result tile [px][c/2], stride 33 words

    int blk  = blockIdx.x;
    int b    = blk / TILES_PER_B;
    int tile = blk - b * TILES_PER_B;
    int rem0 = tile * 64;
    int tid  = threadIdx.x;

    // ---- phase 1: one thread per (pixel, corner) ----
    {
        int px     = tid & 63;
        int corner = tid >> 6;           // 0:(y0,x0) 1:(y0,x1) 2:(y1,x0) 3:(y1,x1)
        int rem = rem0 + px;
        int h   = rem / W_;
        int w   = rem - h * W_;

        const float* fl = flow + b * 2 * HW_ + rem;
        float fx = __ldg(fl);
        float fy = __ldg(fl + HW_);

        float x = (float)w + fx;
        float y = (float)h + fy;

        float x0f = floorf(x);
        float y0f = floorf(y);

        int cx = corner & 1;
        int cy = corner >> 1;

        float wx1 = x - x0f;
        float wy1 = y - y0f;
        float wx = cx ? wx1 : (1.0f - wx1);
        float wy = cy ? wy1 : (1.0f - wy1);

        int xi = (int)x0f + cx;
        int yi = (int)y0f + cy;
        float valid = (xi >= 0 && xi < W_ && yi >= 0 && yi < H_) ? 1.0f : 0.0f;
        xi = min(max(xi, 0), W_ - 1);
        yi = min(max(yi, 0), H_ - 1);

        s_wh[px][corner] = __float2half2_rn(wx * wy * valid);
        s_o[px][corner]  = ((b * H_ + yi) * W_ + xi) * 64;
    }
    __syncthreads();

    // ---- phase 2: 8 warps x 8 pixels; lane covers channels (2*lane, 2*lane+1).
    //      Batched: 16 independent LDGs in flight per thread (4 px x 4 corners),
    //      then blend + conflict-free STS. ----
    {
        int wid  = tid >> 5;
        int lane = tid & 31;

        #pragma unroll
        for (int hblk = 0; hblk < 2; ++hblk) {
            int pbase = wid * 8 + hblk * 4;

            __half2 v[4][4];
            #pragma unroll
            for (int j = 0; j < 4; ++j) {
                int p = pbase + j;
                #pragma unroll
                for (int k = 0; k < 4; ++k)
                    v[j][k] = __ldg((const __half2*)(g_nhwc + s_o[p][k]) + lane);
            }

            #pragma unroll
            for (int j = 0; j < 4; ++j) {
                int p = pbase + j;
                __half2 r = __hfma2(v[j][0], s_wh[p][0],
                            __hfma2(v[j][1], s_wh[p][1],
                            __hfma2(v[j][2], s_wh[p][2],
                            __hmul2(v[j][3], s_wh[p][3]))));
                s_r[p * 33 + lane] = r;
            }
        }
    }
    __syncthreads();

    // ---- phase 3: coalesced NCHW fp32 writeback.
    //      Thread (px = tid&63, cgrp = tid>>6) reads 8 half2 words (stride-33:
    //      conflict-free), stores 16 floats; warps store contiguous 128B lines. ----
    {
        int px   = tid & 63;
        int cgrp = tid >> 6;             // 0..3 -> channels 16*cgrp .. +15
        float* dst = out + b * CHW_ + rem0 + px;
        #pragma unroll
        for (int k = 0; k < 8; ++k) {
            __half2 hv = s_r[px * 33 + cgrp * 8 + k];
            float2 f = __half22float2(hv);
            int c = cgrp * 16 + 2 * k;
            dst[c * HW_]       = f.x;
            dst[(c + 1) * HW_] = f.y;
        }
    }
}

extern "C" void kernel_launch(void* const* d_in, const int* in_sizes, int n_in,
                              void* d_out, int out_size)
{
    const float* img  = (const float*)d_in[0];
    const float* flow = (const float*)d_in[1];
    float* out = (float*)d_out;

    const int blocks = B_ * TILES_PER_B;   // 14336
    nchw_to_nhwc_f16<<<blocks, 256>>>(img);
    warp_gather_f16<<<blocks, 256>>>(flow, out);
}